// round 4
// baseline (speedup 1.0000x reference)
#include <cuda_runtime.h>
#include <cuda_bf16.h>
#include <cstdint>

#define ROW_LEN   4096
#define THREADS   256          // 8 warps, each owns one row
#define WARPS     8
#define V4_ROW    (ROW_LEN / 4)   // 1024 float4 per row
#define ITERS     8               // 1024 / 32 lanes / 4 float4-per-iter

__global__ void __launch_bounds__(THREADS, 8)
quant_warprow_kernel(const float* __restrict__ x, float* __restrict__ out)
{
    const int wid = threadIdx.x >> 5;
    const int lid = threadIdx.x & 31;
    const size_t row  = (size_t)blockIdx.x * WARPS + wid;
    const size_t base = row * ROW_LEN;

    const float4* __restrict__ xr   = reinterpret_cast<const float4*>(x + base);
    float4* __restrict__       outr = reinterpret_cast<float4*>(out + base);

    // ---- Pass 1: stream row, reduce min/max. Default caching -> row parks in L2.
    float mn =  3.4e38f;
    float mx = -3.4e38f;
#pragma unroll
    for (int it = 0; it < ITERS; ++it) {
        // 4 independent LDG.128 in flight per lane
        float4 a = __ldg(&xr[lid + (it * 4 + 0) * 32]);
        float4 b = __ldg(&xr[lid + (it * 4 + 1) * 32]);
        float4 c = __ldg(&xr[lid + (it * 4 + 2) * 32]);
        float4 d = __ldg(&xr[lid + (it * 4 + 3) * 32]);
        mn = fminf(mn, fminf(fminf(a.x, a.y), fminf(a.z, a.w)));
        mx = fmaxf(mx, fmaxf(fmaxf(a.x, a.y), fmaxf(a.z, a.w)));
        mn = fminf(mn, fminf(fminf(b.x, b.y), fminf(b.z, b.w)));
        mx = fmaxf(mx, fmaxf(fmaxf(b.x, b.y), fmaxf(b.z, b.w)));
        mn = fminf(mn, fminf(fminf(c.x, c.y), fminf(c.z, c.w)));
        mx = fmaxf(mx, fmaxf(fmaxf(c.x, c.y), fmaxf(c.z, c.w)));
        mn = fminf(mn, fminf(fminf(d.x, d.y), fminf(d.z, d.w)));
        mx = fmaxf(mx, fmaxf(fmaxf(d.x, d.y), fmaxf(d.z, d.w)));
    }

    // ---- Warp-only reduce: no smem, no block barrier, warps fully independent.
#pragma unroll
    for (int off = 16; off > 0; off >>= 1) {
        mn = fminf(mn, __shfl_xor_sync(0xFFFFFFFFu, mn, off));
        mx = fmaxf(mx, __shfl_xor_sync(0xFFFFFFFFu, mx, off));
    }

    float scale = (mx - mn) * (1.0f / 255.0f);
    scale = fminf(fmaxf(scale, 1e-5f), 1e4f);
    float zp = -mn / scale;
    zp = fminf(fmaxf(zp, -1e4f), 1e4f);
    const float inv = 1.0f / scale;

    // ---- Pass 2: re-read from L2 (evict-first: data is dead after this),
    //      quant-dequant, streaming stores.
#pragma unroll
    for (int it = 0; it < ITERS; ++it) {
#pragma unroll
        for (int j = 0; j < 4; ++j) {
            const int idx = lid + (it * 4 + j) * 32;
            float4 v = __ldcs(&xr[idx]);
            float4 r;
            float q;
            q = rintf(v.x * inv) + zp; q = fminf(fmaxf(q, 0.0f), 255.0f); r.x = (q - zp) * scale;
            q = rintf(v.y * inv) + zp; q = fminf(fmaxf(q, 0.0f), 255.0f); r.y = (q - zp) * scale;
            q = rintf(v.z * inv) + zp; q = fminf(fmaxf(q, 0.0f), 255.0f); r.z = (q - zp) * scale;
            q = rintf(v.w * inv) + zp; q = fminf(fmaxf(q, 0.0f), 255.0f); r.w = (q - zp) * scale;
            __stcs(&outr[idx], r);
        }
    }
}

extern "C" void kernel_launch(void* const* d_in, const int* in_sizes, int n_in,
                              void* d_out, int out_size)
{
    const float* x = (const float*)d_in[0];
    float* out = (float*)d_out;
    const int n_rows = in_sizes[0] / ROW_LEN;       // 16384
    const int n_blocks = n_rows / WARPS;            // 2048
    quant_warprow_kernel<<<n_blocks, THREADS>>>(x, out);
}

// round 5
// speedup vs baseline: 1.4061x; 1.4061x over previous
#include <cuda_runtime.h>
#include <cuda_bf16.h>
#include <cstdint>

#define ROW_LEN 4096
#define THREADS 256
#define V4 4                    // 4096 / 4 / 256
#define ROW_BYTES (ROW_LEN * 4) // 16384

__global__ void __launch_bounds__(THREADS, 8)
quant_rowwise_tma(const float* __restrict__ x, float* __restrict__ out)
{
    __shared__ alignas(128) float4 sbuf[ROW_LEN / 4];   // 16 KB staging for the output row
    __shared__ float smn[8], smx[8];

    const size_t base = (size_t)blockIdx.x * ROW_LEN;
    const float4* __restrict__ xr = reinterpret_cast<const float4*>(x + base);
    float* outp = out + base;

    const int t = threadIdx.x;

    // ---- front-batched vector loads into registers (as R3) ----
    float4 v[V4];
#pragma unroll
    for (int k = 0; k < V4; ++k)
        v[k] = __ldcs(&xr[t + k * THREADS]);

    // ---- local + warp min/max ----
    float mn = v[0].x, mx = v[0].x;
#pragma unroll
    for (int k = 0; k < V4; ++k) {
        mn = fminf(mn, fminf(fminf(v[k].x, v[k].y), fminf(v[k].z, v[k].w)));
        mx = fmaxf(mx, fmaxf(fmaxf(v[k].x, v[k].y), fmaxf(v[k].z, v[k].w)));
    }
#pragma unroll
    for (int off = 16; off > 0; off >>= 1) {
        mn = fminf(mn, __shfl_xor_sync(0xFFFFFFFFu, mn, off));
        mx = fmaxf(mx, __shfl_xor_sync(0xFFFFFFFFu, mx, off));
    }

    const int wid = t >> 5, lid = t & 31;
    if (lid == 0) { smn[wid] = mn; smx[wid] = mx; }
    __syncthreads();

    // every thread folds the 8 partials redundantly (no second barrier)
    float bmn = smn[0], bmx = smx[0];
#pragma unroll
    for (int i = 1; i < 8; ++i) {
        bmn = fminf(bmn, smn[i]);
        bmx = fmaxf(bmx, smx[i]);
    }
    float scale = (bmx - bmn) * (1.0f / 255.0f);
    scale = fminf(fmaxf(scale, 1e-5f), 1e4f);
    float zp = -bmn / scale;
    zp = fminf(fmaxf(zp, -1e4f), 1e4f);
    const float inv = 1.0f / scale;

    // ---- quant-dequant into smem staging ----
#pragma unroll
    for (int k = 0; k < V4; ++k) {
        float4 r;
        float q;
        q = rintf(v[k].x * inv) + zp; q = fminf(fmaxf(q, 0.0f), 255.0f); r.x = (q - zp) * scale;
        q = rintf(v[k].y * inv) + zp; q = fminf(fmaxf(q, 0.0f), 255.0f); r.y = (q - zp) * scale;
        q = rintf(v[k].z * inv) + zp; q = fminf(fmaxf(q, 0.0f), 255.0f); r.z = (q - zp) * scale;
        q = rintf(v[k].w * inv) + zp; q = fminf(fmaxf(q, 0.0f), 255.0f); r.w = (q - zp) * scale;
        sbuf[t + k * THREADS] = r;
    }
    __syncthreads();

    // ---- single 16 KB bulk store: smem -> global (one contiguous DRAM burst) ----
    if (t == 0) {
        // order generic-proxy STS before async-proxy bulk copy
        asm volatile("fence.proxy.async.shared::cta;" ::: "memory");
        uint32_t s_addr;
        asm("{ .reg .u64 tmp; cvta.to.shared.u64 tmp, %1; cvt.u32.u64 %0, tmp; }"
            : "=r"(s_addr) : "l"(sbuf));
        asm volatile(
            "cp.async.bulk.global.shared::cta.bulk_group [%0], [%1], %2;"
            :: "l"(outp), "r"(s_addr), "n"(ROW_BYTES) : "memory");
        asm volatile("cp.async.bulk.commit_group;" ::: "memory");
        asm volatile("cp.async.bulk.wait_group 0;" ::: "memory");
    }
}

extern "C" void kernel_launch(void* const* d_in, const int* in_sizes, int n_in,
                              void* d_out, int out_size)
{
    const float* x = (const float*)d_in[0];
    float* out = (float*)d_out;
    const int n_rows = in_sizes[0] / ROW_LEN;   // 16384
    quant_rowwise_tma<<<n_rows, THREADS>>>(x, out);
}